// round 1
// baseline (speedup 1.0000x reference)
#include <cuda_runtime.h>
#include <cuda_bf16.h>

// Shapes (fixed by the problem)
#define CH    32
#define DD    36
#define HH    48
#define WW    48
#define HW    (HH*WW)          // 2304
#define DHW   (DD*HW)          // 82944
#define PP    9
#define P2    81
#define ND    (DD/PP)          // 4
#define NW    (HW/PP)          // 256
#define LL    (ND*NW)          // 1024
#define M2    162              // 2*P2

// ---------------- device scratch (no allocs allowed) ----------------
__device__ float g_weff[P2 * P2];                 // folded W2@W1  (81x81)
__device__ float g_ux[CH * LL * P2];              // conv+unfold of x
__device__ float g_uy[CH * LL * P2];              // conv+unfold of y
__device__ float g_px[CH * LL * P2];              // res_trans(ux)
__device__ float g_py[CH * LL * P2];              // res_trans(uy)

// ---------------- f32x2 packed math helpers ----------------
__device__ __forceinline__ unsigned long long ffma2(unsigned long long a,
                                                    unsigned long long b,
                                                    unsigned long long c) {
    unsigned long long d;
    asm("fma.rn.f32x2 %0, %1, %2, %3;" : "=l"(d) : "l"(a), "l"(b), "l"(c));
    return d;
}
__device__ __forceinline__ unsigned long long dup2(float a) {
    unsigned long long d;
    asm("mov.b64 %0, {%1, %1};" : "=l"(d) : "f"(a));
    return d;
}
__device__ __forceinline__ float2 unpack2(unsigned long long v) {
    float2 r;
    asm("mov.b64 {%0, %1}, %2;" : "=f"(r.x), "=f"(r.y) : "l"(v));
    return r;
}

// ---------------- Kernel 0: Weff = W2 @ W1 ----------------
// W1: (162, 81), W2: (81, 162).  Weff[k][j] = sum_m W2[k,m] * W1[m,j]
__global__ void weff_kernel(const float* __restrict__ W1,
                            const float* __restrict__ W2,
                            float* __restrict__ We) {
    __shared__ float w2row[M2];
    int k = blockIdx.x;     // 0..80
    int j = threadIdx.x;    // 0..80
    for (int m = j; m < M2; m += P2) w2row[m] = W2[k * M2 + m];
    __syncthreads();
    float s = 0.f;
    #pragma unroll 6
    for (int m = 0; m < M2; m++) s += w2row[m] * W1[m * P2 + j];
    We[k * P2 + j] = s;
}

// ---------------- Kernel 1: 1x1x1 conv + unfold-permute ----------------
// x: (32, 36, 2304) contiguous.  U out: (C, L, 81) in unfold order.
__global__ __launch_bounds__(256)
void conv_unfold(const float* __restrict__ x, const float* __restrict__ Wc,
                 const float* __restrict__ bc, float* __restrict__ U) {
    __shared__ float Ws[CH * CH];
    __shared__ float bs[CH];
    int tid = threadIdx.x;
    for (int i = tid; i < CH * CH; i += 256) Ws[i] = Wc[i];
    if (tid < CH) bs[tid] = bc[tid];
    __syncthreads();

    int p = blockIdx.x * 256 + tid;           // voxel index 0..82943
    float xv[CH];
    #pragma unroll
    for (int i = 0; i < CH; i++) xv[i] = x[i * DHW + p];

    // dest coordinates (unfold ordering)
    int d  = p / HW;
    int hw = p - d * HW;
    int pd = d / PP, kd = d - pd * PP;
    int pw = hw / PP, kw = hw - pw * PP;
    int l  = pd * NW + pw;
    int j  = kd * PP + kw;

    #pragma unroll 4
    for (int c = 0; c < CH; c++) {
        const float4* wr = (const float4*)&Ws[c * CH];
        float s = bs[c];
        #pragma unroll
        for (int q = 0; q < CH / 4; q++) {
            float4 w = wr[q];
            s += w.x * xv[4*q] + w.y * xv[4*q+1] + w.z * xv[4*q+2] + w.w * xv[4*q+3];
        }
        U[(c * LL + l) * P2 + j] = s;
    }
}

// ---------------- Kernel 2: folded res_trans + LeakyReLU ----------------
// P[c,l,k] = leaky( sum_j U[c,l,j] * Weff[k,j] )
__global__ __launch_bounds__(256)
void res_trans_kernel(const float* __restrict__ U, float* __restrict__ Pout) {
    __shared__ float We[P2 * P2];   // 26 KB
    __shared__ float Us[CH * P2];   // 10.4 KB
    int l = blockIdx.x;
    int tid = threadIdx.x;
    for (int i = tid; i < P2 * P2; i += 256) We[i] = g_weff[i];
    for (int i = tid; i < CH * P2; i += 256) {
        int c = i / P2, j = i - c * P2;
        Us[i] = U[(c * LL + l) * P2 + j];
    }
    __syncthreads();
    for (int idx = tid; idx < CH * P2; idx += 256) {
        int c = idx / P2, k = idx - c * P2;
        const float* ur = &Us[c * P2];
        const float* wr = &We[k * P2];
        float s = 0.f;
        #pragma unroll
        for (int j = 0; j < P2; j++) s += ur[j] * wr[j];
        s = (s > 0.f) ? s : 0.2f * s;
        Pout[(c * LL + l) * P2 + k] = s;
    }
}

// ---------------- Kernel 3: att GEMM  C[c] = px[c] @ py[c]^T / 81 ----------
// 128x128 tile, 256 threads, 8x8 microtile with packed f32x2 FMA.
#define BM 128
#define BN 128
#define SPAD 132               // [k][m] smem row stride (16B-aligned, conflict-light)
#define ATT_SMEM (2 * P2 * SPAD * 4)

__global__ __launch_bounds__(256, 2)
void att_gemm(const float* __restrict__ px, const float* __restrict__ py,
              float* __restrict__ att) {
    extern __shared__ float sm[];
    float* As = sm;                 // [81][132]
    float* Bs = sm + P2 * SPAD;     // [81][132]

    int c  = blockIdx.z;
    int mb = blockIdx.y * BM;
    int nb = blockIdx.x * BN;
    const float* A = px + c * (LL * P2);
    const float* B = py + c * (LL * P2);
    int tid = threadIdx.x;

    // load tiles, transposing to [k][m] (gmem coalesced along k)
    for (int idx = tid; idx < BM * P2; idx += 256) {
        int r = idx / P2, k = idx - r * P2;
        As[k * SPAD + r] = A[(mb + r) * P2 + k];
        Bs[k * SPAD + r] = B[(nb + r) * P2 + k];
    }
    __syncthreads();

    int tx = tid & 15, ty = tid >> 4;
    const float* Arow = As + ty * 8;
    const float* Brow = Bs + tx * 8;

    unsigned long long acc[8][4];
    #pragma unroll
    for (int i = 0; i < 8; i++)
        #pragma unroll
        for (int j = 0; j < 4; j++) acc[i][j] = 0ull;

    for (int k = 0; k < P2; k++) {
        float4 a0 = *(const float4*)(Arow + k * SPAD);
        float4 a1 = *(const float4*)(Arow + k * SPAD + 4);
        ulonglong2 b0 = *(const ulonglong2*)(Brow + k * SPAD);
        ulonglong2 b1 = *(const ulonglong2*)(Brow + k * SPAD + 4);
        unsigned long long bv[4] = {b0.x, b0.y, b1.x, b1.y};
        unsigned long long ad[8];
        ad[0] = dup2(a0.x); ad[1] = dup2(a0.y); ad[2] = dup2(a0.z); ad[3] = dup2(a0.w);
        ad[4] = dup2(a1.x); ad[5] = dup2(a1.y); ad[6] = dup2(a1.z); ad[7] = dup2(a1.w);
        #pragma unroll
        for (int i = 0; i < 8; i++)
            #pragma unroll
            for (int j = 0; j < 4; j++)
                acc[i][j] = ffma2(ad[i], bv[j], acc[i][j]);
    }

    const float scale = 1.0f / 81.0f;
    #pragma unroll
    for (int i = 0; i < 8; i++) {
        int row = mb + ty * 8 + i;
        float* o = att + c * (LL * LL) + row * LL + nb + tx * 8;
        float2 u0 = unpack2(acc[i][0]);
        float2 u1 = unpack2(acc[i][1]);
        float2 u2 = unpack2(acc[i][2]);
        float2 u3 = unpack2(acc[i][3]);
        float4 v0 = make_float4(u0.x * scale, u0.y * scale, u1.x * scale, u1.y * scale);
        float4 v1 = make_float4(u2.x * scale, u2.y * scale, u3.x * scale, u3.y * scale);
        *(float4*)(o)     = v0;
        *(float4*)(o + 4) = v1;
    }
}

// ---------------- launch ----------------
extern "C" void kernel_launch(void* const* d_in, const int* in_sizes, int n_in,
                              void* d_out, int out_size) {
    const float* x     = (const float*)d_in[0];
    const float* y     = (const float*)d_in[1];
    const float* W_img = (const float*)d_in[2];
    const float* b_img = (const float*)d_in[3];
    const float* W_fea = (const float*)d_in[4];
    const float* b_fea = (const float*)d_in[5];
    const float* W1    = (const float*)d_in[6];
    const float* W2    = (const float*)d_in[7];
    float* out = (float*)d_out;

    float *weff, *ux, *uy, *px, *py;
    cudaGetSymbolAddress((void**)&weff, g_weff);
    cudaGetSymbolAddress((void**)&ux,   g_ux);
    cudaGetSymbolAddress((void**)&uy,   g_uy);
    cudaGetSymbolAddress((void**)&px,   g_px);
    cudaGetSymbolAddress((void**)&py,   g_py);

    static bool attr_set = false;
    if (!attr_set) {
        cudaFuncSetAttribute(att_gemm, cudaFuncAttributeMaxDynamicSharedMemorySize,
                             ATT_SMEM);
        attr_set = true;
    }

    weff_kernel<<<P2, P2>>>(W1, W2, weff);
    conv_unfold<<<DHW / 256, 256>>>(x, W_img, b_img, ux);
    conv_unfold<<<DHW / 256, 256>>>(y, W_fea, b_fea, uy);
    res_trans_kernel<<<LL, 256>>>(ux, px);
    res_trans_kernel<<<LL, 256>>>(uy, py);

    dim3 grid(LL / BN, LL / BM, CH);   // (8, 8, 32)
    att_gemm<<<grid, 256, ATT_SMEM>>>(px, py, out);
}

// round 2
// speedup vs baseline: 1.4252x; 1.4252x over previous
#include <cuda_runtime.h>
#include <cuda_bf16.h>

// Shapes (fixed by the problem)
#define CH    32
#define DD    36
#define HH    48
#define WW    48
#define HW    (HH*WW)          // 2304
#define DHW   (DD*HW)          // 82944
#define PP    9
#define P2    81
#define ND    (DD/PP)          // 4
#define NW    (HW/PP)          // 256
#define LL    (ND*NW)          // 1024
#define M2    162              // 2*P2

// ---------------- device scratch (no allocs allowed) ----------------
__device__ float g_wefft[P2 * P2];                // Wefft[j][k] = (W2@W1)[k][j]
__device__ float g_ux[CH * P2 * LL];              // Ut[c][j][l]  (K-major)
__device__ float g_uy[CH * P2 * LL];
__device__ float g_px[CH * P2 * LL];              // pxT[c][k][l] (K-major)
__device__ float g_py[CH * P2 * LL];

// ---------------- f32x2 packed math helpers ----------------
__device__ __forceinline__ unsigned long long ffma2(unsigned long long a,
                                                    unsigned long long b,
                                                    unsigned long long c) {
    unsigned long long d;
    asm("fma.rn.f32x2 %0, %1, %2, %3;" : "=l"(d) : "l"(a), "l"(b), "l"(c));
    return d;
}
__device__ __forceinline__ unsigned long long dup2(float a) {
    unsigned long long d;
    asm("mov.b64 %0, {%1, %1};" : "=l"(d) : "f"(a));
    return d;
}
__device__ __forceinline__ float2 unpack2(unsigned long long v) {
    float2 r;
    asm("mov.b64 {%0, %1}, %2;" : "=f"(r.x), "=f"(r.y) : "l"(v));
    return r;
}

// ---------------- Kernel 0: Wefft[j][k] = (W2 @ W1)[k][j] ----------------
__global__ void weff_kernel(const float* __restrict__ W1,
                            const float* __restrict__ W2,
                            float* __restrict__ WeT) {
    __shared__ float w2row[M2];
    int k = blockIdx.x;     // 0..80 output row of Weff
    int j = threadIdx.x;    // 0..80
    for (int m = j; m < M2; m += P2) w2row[m] = W2[k * M2 + m];
    __syncthreads();
    float s = 0.f;
    #pragma unroll 6
    for (int m = 0; m < M2; m++) s += w2row[m] * W1[m * P2 + j];
    WeT[j * P2 + k] = s;    // transposed store
}

// ---------------- Kernel 1: 1x1x1 conv + unfold, K-major output -----------
// Block owns one patch-offset j; threads cover 256 consecutive l.
// Writes Ut[(c*81 + j)*1024 + l]  -> fully coalesced.
__global__ __launch_bounds__(256)
void conv_unfold(const float* __restrict__ x, const float* __restrict__ Wc,
                 const float* __restrict__ bc, float* __restrict__ U) {
    __shared__ float Ws[CH * CH];
    __shared__ float bs[CH];
    int tid = threadIdx.x;
    for (int i = tid; i < CH * CH; i += 256) Ws[i] = Wc[i];
    if (tid < CH) bs[tid] = bc[tid];
    __syncthreads();

    int j  = blockIdx.x;                // 0..80
    int l  = blockIdx.y * 256 + tid;    // 0..1023
    int kd = j / PP, kw = j - kd * PP;
    int pd = l >> 8, pw = l & 255;
    int p  = (pd * PP + kd) * HW + pw * PP + kw;   // source voxel

    float xv[CH];
    #pragma unroll
    for (int i = 0; i < CH; i++) xv[i] = x[i * DHW + p];

    #pragma unroll 4
    for (int c = 0; c < CH; c++) {
        const float4* wr = (const float4*)&Ws[c * CH];
        float s = bs[c];
        #pragma unroll
        for (int q = 0; q < CH / 4; q++) {
            float4 w = wr[q];
            s += w.x * xv[4*q] + w.y * xv[4*q+1] + w.z * xv[4*q+2] + w.w * xv[4*q+3];
        }
        U[(c * P2 + j) * LL + l] = s;
    }
}

// ---------------- Kernel 2: folded res_trans + LeakyReLU (GEMM) -----------
// out[c][k][l] = leaky( sum_j Ut[c][j][l] * Wefft[j][k] ), K-major in, K-major out.
// Block: 128 l-rows of one channel. Microtile 8(m) x 6(n) with f32x2.
#define RT_SMEM ((P2 * 128 + P2 * 96) * 4)     // 72576 B
__global__ __launch_bounds__(256, 2)
void res_trans_kernel(const float* __restrict__ U, float* __restrict__ Pout) {
    extern __shared__ float sm[];
    float* As = sm;                 // [81][128]
    float* Bs = sm + P2 * 128;      // [81][96] (cols >=81 zero)

    int c  = blockIdx.y;
    int mb = blockIdx.x * 128;
    int tid = threadIdx.x;
    const float* A = U + c * (P2 * LL);

    for (int idx = tid; idx < P2 * 128; idx += 256) {
        int jj = idx >> 7, m = idx & 127;
        As[idx] = A[jj * LL + mb + m];
    }
    for (int idx = tid; idx < P2 * 96; idx += 256) {
        int jj = idx / 96, n = idx - jj * 96;
        Bs[idx] = (n < P2) ? g_wefft[jj * P2 + n] : 0.f;
    }
    __syncthreads();

    int tx = tid & 15, ty = tid >> 4;
    int m0 = ty * 8, n0 = tx * 6;

    unsigned long long acc[8][3];
    #pragma unroll
    for (int i = 0; i < 8; i++)
        #pragma unroll
        for (int jj = 0; jj < 3; jj++) acc[i][jj] = 0ull;

    #pragma unroll 3
    for (int j = 0; j < P2; j++) {
        float4 a0 = *(const float4*)(As + j * 128 + m0);
        float4 a1 = *(const float4*)(As + j * 128 + m0 + 4);
        const unsigned long long* bp =
            (const unsigned long long*)(Bs + j * 96 + n0);
        unsigned long long b0 = bp[0], b1 = bp[1], b2 = bp[2];
        unsigned long long ad[8];
        ad[0] = dup2(a0.x); ad[1] = dup2(a0.y); ad[2] = dup2(a0.z); ad[3] = dup2(a0.w);
        ad[4] = dup2(a1.x); ad[5] = dup2(a1.y); ad[6] = dup2(a1.z); ad[7] = dup2(a1.w);
        #pragma unroll
        for (int i = 0; i < 8; i++) {
            acc[i][0] = ffma2(ad[i], b0, acc[i][0]);
            acc[i][1] = ffma2(ad[i], b1, acc[i][1]);
            acc[i][2] = ffma2(ad[i], b2, acc[i][2]);
        }
    }

    float* O = Pout + c * (P2 * LL);
    #pragma unroll
    for (int nl = 0; nl < 6; nl++) {
        int n = n0 + nl;
        if (n < P2) {
            float v[8];
            #pragma unroll
            for (int i = 0; i < 8; i++) {
                float2 u = unpack2(acc[i][nl >> 1]);
                float s = (nl & 1) ? u.y : u.x;
                v[i] = (s > 0.f) ? s : 0.2f * s;
            }
            float* o = O + n * LL + mb + m0;
            *(float4*)(o)     = make_float4(v[0], v[1], v[2], v[3]);
            *(float4*)(o + 4) = make_float4(v[4], v[5], v[6], v[7]);
        }
    }
}

// ---------------- Kernel 3: att GEMM  C[c] = pxT^T @ pyT / 81 -------------
// Tiles are K-major in gmem -> straight coalesced copy, conflict-free STS.
#define BM 128
#define BN 128
#define ATT_SMEM (2 * P2 * 128 * 4)     // 82944 B
__global__ __launch_bounds__(256, 2)
void att_gemm(const float* __restrict__ px, const float* __restrict__ py,
              float* __restrict__ att) {
    extern __shared__ float sm[];
    float* As = sm;                 // [81][128]
    float* Bs = sm + P2 * 128;      // [81][128]

    int c  = blockIdx.z;
    int mb = blockIdx.y * BM;
    int nb = blockIdx.x * BN;
    const float* A = px + c * (P2 * LL);
    const float* B = py + c * (P2 * LL);
    int tid = threadIdx.x;

    for (int idx = tid; idx < BM * P2; idx += 256) {
        int k = idx >> 7, m = idx & 127;
        As[idx] = A[k * LL + mb + m];
        Bs[idx] = B[k * LL + nb + m];
    }
    __syncthreads();

    int tx = tid & 15, ty = tid >> 4;
    int m0 = ty * 8, n0 = tx * 8;

    unsigned long long acc[8][4];
    #pragma unroll
    for (int i = 0; i < 8; i++)
        #pragma unroll
        for (int j = 0; j < 4; j++) acc[i][j] = 0ull;

    #pragma unroll 3
    for (int k = 0; k < P2; k++) {
        float4 a0 = *(const float4*)(As + k * 128 + m0);
        float4 a1 = *(const float4*)(As + k * 128 + m0 + 4);
        ulonglong2 b0 = *(const ulonglong2*)(Bs + k * 128 + n0);
        ulonglong2 b1 = *(const ulonglong2*)(Bs + k * 128 + n0 + 4);
        unsigned long long bv[4] = {b0.x, b0.y, b1.x, b1.y};
        unsigned long long ad[8];
        ad[0] = dup2(a0.x); ad[1] = dup2(a0.y); ad[2] = dup2(a0.z); ad[3] = dup2(a0.w);
        ad[4] = dup2(a1.x); ad[5] = dup2(a1.y); ad[6] = dup2(a1.z); ad[7] = dup2(a1.w);
        #pragma unroll
        for (int i = 0; i < 8; i++)
            #pragma unroll
            for (int j = 0; j < 4; j++)
                acc[i][j] = ffma2(ad[i], bv[j], acc[i][j]);
    }

    const float scale = 1.0f / 81.0f;
    #pragma unroll
    for (int i = 0; i < 8; i++) {
        int row = mb + m0 + i;
        float* o = att + c * (LL * LL) + row * LL + nb + n0;
        float2 u0 = unpack2(acc[i][0]);
        float2 u1 = unpack2(acc[i][1]);
        float2 u2 = unpack2(acc[i][2]);
        float2 u3 = unpack2(acc[i][3]);
        *(float4*)(o)     = make_float4(u0.x * scale, u0.y * scale, u1.x * scale, u1.y * scale);
        *(float4*)(o + 4) = make_float4(u2.x * scale, u2.y * scale, u3.x * scale, u3.y * scale);
    }
}

// ---------------- launch ----------------
extern "C" void kernel_launch(void* const* d_in, const int* in_sizes, int n_in,
                              void* d_out, int out_size) {
    const float* x     = (const float*)d_in[0];
    const float* y     = (const float*)d_in[1];
    const float* W_img = (const float*)d_in[2];
    const float* b_img = (const float*)d_in[3];
    const float* W_fea = (const float*)d_in[4];
    const float* b_fea = (const float*)d_in[5];
    const float* W1    = (const float*)d_in[6];
    const float* W2    = (const float*)d_in[7];
    float* out = (float*)d_out;

    float *weT, *ux, *uy, *px, *py;
    cudaGetSymbolAddress((void**)&weT, g_wefft);
    cudaGetSymbolAddress((void**)&ux,  g_ux);
    cudaGetSymbolAddress((void**)&uy,  g_uy);
    cudaGetSymbolAddress((void**)&px,  g_px);
    cudaGetSymbolAddress((void**)&py,  g_py);

    static bool attr_set = false;
    if (!attr_set) {
        cudaFuncSetAttribute(att_gemm, cudaFuncAttributeMaxDynamicSharedMemorySize,
                             ATT_SMEM);
        cudaFuncSetAttribute(res_trans_kernel,
                             cudaFuncAttributeMaxDynamicSharedMemorySize, RT_SMEM);
        attr_set = true;
    }

    weff_kernel<<<P2, P2>>>(W1, W2, weT);
    {
        dim3 g(P2, LL / 256);
        conv_unfold<<<g, 256>>>(x, W_img, b_img, ux);
        conv_unfold<<<g, 256>>>(y, W_fea, b_fea, uy);
    }
    {
        dim3 g(LL / 128, CH);
        res_trans_kernel<<<g, 256, RT_SMEM>>>(ux, px);
        res_trans_kernel<<<g, 256, RT_SMEM>>>(uy, py);
    }
    dim3 grid(LL / BN, LL / BM, CH);   // (8, 8, 32)
    att_gemm<<<grid, 256, ATT_SMEM>>>(px, py, out);
}

// round 5
// speedup vs baseline: 1.6284x; 1.1426x over previous
#include <cuda_runtime.h>
#include <cuda_bf16.h>
#include <cstdint>

// Shapes (fixed by the problem)
#define CH    32
#define DD    36
#define HH    48
#define WW    48
#define HW    (HH*WW)          // 2304
#define DHW   (DD*HW)          // 82944
#define PP    9
#define P2    81
#define ND    (DD/PP)          // 4
#define NW    (HW/PP)          // 256
#define LL    (ND*NW)          // 1024
#define M2    162              // 2*P2
#define KE    256              // extended K: [hi(81) | s1(81) | s2(81) | 13 zero pad]

// ---------------- device scratch (no allocs allowed) ----------------
__device__ float g_wefft[P2 * P2];                  // Wefft[j][k] = (W2@W1)[k][j]
__device__ float g_ux[CH * P2 * LL];                // Ut[c][j][l] (K-major, fp32)
__device__ float g_uy[CH * P2 * LL];
__device__ __nv_bfloat16 g_pA[CH * LL * KE];        // A rows: [hi, lo, hi, 0]
__device__ __nv_bfloat16 g_pB[CH * LL * KE];        // B rows: [hi, hi, lo, 0]

// ---------------- f32x2 packed math helpers ----------------
__device__ __forceinline__ unsigned long long ffma2(unsigned long long a,
                                                    unsigned long long b,
                                                    unsigned long long c) {
    unsigned long long d;
    asm("fma.rn.f32x2 %0, %1, %2, %3;" : "=l"(d) : "l"(a), "l"(b), "l"(c));
    return d;
}
__device__ __forceinline__ unsigned long long dup2(float a) {
    unsigned long long d;
    asm("mov.b64 %0, {%1, %1};" : "=l"(d) : "f"(a));
    return d;
}
__device__ __forceinline__ float2 unpack2(unsigned long long v) {
    float2 r;
    asm("mov.b64 {%0, %1}, %2;" : "=f"(r.x), "=f"(r.y) : "l"(v));
    return r;
}

// ---------------- async / mma helpers (plain-target safe) ----------------
__device__ __forceinline__ uint32_t smem_u32(const void* p) {
    uint32_t a;
    asm("{ .reg .u64 t; cvta.to.shared.u64 t, %1; cvt.u32.u64 %0, t; }"
        : "=r"(a) : "l"(p));
    return a;
}
__device__ __forceinline__ void cpa16(uint32_t s, const void* g) {
    asm volatile("cp.async.cg.shared.global [%0], [%1], 16;" :: "r"(s), "l"(g));
}
__device__ __forceinline__ void ldmx4(uint32_t& r0, uint32_t& r1,
                                      uint32_t& r2, uint32_t& r3, uint32_t a) {
    asm volatile("ldmatrix.sync.aligned.m8n8.x4.shared.b16 {%0,%1,%2,%3}, [%4];"
                 : "=r"(r0), "=r"(r1), "=r"(r2), "=r"(r3) : "r"(a));
}
__device__ __forceinline__ void mma16816(float* d, const uint32_t* a,
                                         uint32_t b0, uint32_t b1) {
    asm volatile(
        "mma.sync.aligned.m16n8k16.row.col.f32.bf16.bf16.f32 "
        "{%0,%1,%2,%3}, {%4,%5,%6,%7}, {%8,%9}, {%0,%1,%2,%3};"
        : "+f"(d[0]), "+f"(d[1]), "+f"(d[2]), "+f"(d[3])
        : "r"(a[0]), "r"(a[1]), "r"(a[2]), "r"(a[3]), "r"(b0), "r"(b1));
}

// ---------------- Kernel 0: Wefft[j][k] = (W2 @ W1)[k][j] ----------------
__global__ void weff_kernel(const float* __restrict__ W1,
                            const float* __restrict__ W2,
                            float* __restrict__ WeT) {
    __shared__ float w2row[M2];
    int k = blockIdx.x;
    int j = threadIdx.x;
    for (int m = j; m < M2; m += P2) w2row[m] = W2[k * M2 + m];
    __syncthreads();
    float s = 0.f;
    #pragma unroll 6
    for (int m = 0; m < M2; m++) s += w2row[m] * W1[m * P2 + j];
    WeT[j * P2 + k] = s;
}

// ---------------- Kernel 1: 1x1x1 conv + unfold, K-major, x/y merged ------
__global__ __launch_bounds__(256)
void conv_unfold(const float* __restrict__ x, const float* __restrict__ y,
                 const float* __restrict__ Wi, const float* __restrict__ bi,
                 const float* __restrict__ Wf, const float* __restrict__ bf_,
                 float* __restrict__ ux, float* __restrict__ uy) {
    int z = blockIdx.z;
    const float* src = z ? y : x;
    const float* Wc  = z ? Wf : Wi;
    const float* bc  = z ? bf_ : bi;
    float* U         = z ? uy : ux;

    __shared__ float Ws[CH * CH];
    __shared__ float bs[CH];
    int tid = threadIdx.x;
    for (int i = tid; i < CH * CH; i += 256) Ws[i] = Wc[i];
    if (tid < CH) bs[tid] = bc[tid];
    __syncthreads();

    int j  = blockIdx.x;                // 0..80
    int l  = blockIdx.y * 256 + tid;    // 0..1023
    int kd = j / PP, kw = j - kd * PP;
    int pd = l >> 8, pw = l & 255;
    int p  = (pd * PP + kd) * HW + pw * PP + kw;

    float xv[CH];
    #pragma unroll
    for (int i = 0; i < CH; i++) xv[i] = src[i * DHW + p];

    #pragma unroll 4
    for (int c = 0; c < CH; c++) {
        const float4* wr = (const float4*)&Ws[c * CH];
        float s = bs[c];
        #pragma unroll
        for (int q = 0; q < CH / 4; q++) {
            float4 w = wr[q];
            s += w.x * xv[4*q] + w.y * xv[4*q+1] + w.z * xv[4*q+2] + w.w * xv[4*q+3];
        }
        U[(c * P2 + j) * LL + l] = s;
    }
}

// ---------------- Kernel 2: folded res_trans + LeakyReLU + bf16 split -----
// out row (c,l): bf16[256]  A-variant: [hi|lo|hi|0]  B-variant: [hi|hi|lo|0]
#define RT_BM 64
#define RT_SMEM ((P2 * RT_BM + P2 * 96) * 4)     // 51840 B
__global__ __launch_bounds__(256)
void res_trans_kernel(const float* __restrict__ U0, const float* __restrict__ U1,
                      __nv_bfloat16* __restrict__ P0, __nv_bfloat16* __restrict__ P1) {
    extern __shared__ float sm[];
    float* As = sm;                   // [81][64]
    float* Bs = sm + P2 * RT_BM;      // [81][96] (cols >= 81 zero)

    int z  = blockIdx.z;
    const float* U = z ? U1 : U0;
    __nv_bfloat16* Pout = z ? P1 : P0;

    int c  = blockIdx.y;
    int mb = blockIdx.x * RT_BM;
    int tid = threadIdx.x;
    const float* A = U + c * (P2 * LL);

    for (int idx = tid; idx < P2 * RT_BM; idx += 256) {
        int jj = idx >> 6, m = idx & 63;
        As[idx] = A[jj * LL + mb + m];
    }
    for (int idx = tid; idx < P2 * 96; idx += 256) {
        int jj = idx / 96, n = idx - jj * 96;
        Bs[idx] = (n < P2) ? g_wefft[jj * P2 + n] : 0.f;
    }
    __syncthreads();

    int tx = tid & 15, ty = tid >> 4;
    int m0 = ty * 4, n0 = tx * 6;

    unsigned long long acc[4][3];
    #pragma unroll
    for (int i = 0; i < 4; i++)
        #pragma unroll
        for (int jj = 0; jj < 3; jj++) acc[i][jj] = 0ull;

    #pragma unroll 3
    for (int j = 0; j < P2; j++) {
        float4 a0 = *(const float4*)(As + j * RT_BM + m0);
        const unsigned long long* bp =
            (const unsigned long long*)(Bs + j * 96 + n0);
        unsigned long long b0 = bp[0], b1 = bp[1], b2 = bp[2];
        unsigned long long ad[4];
        ad[0] = dup2(a0.x); ad[1] = dup2(a0.y); ad[2] = dup2(a0.z); ad[3] = dup2(a0.w);
        #pragma unroll
        for (int i = 0; i < 4; i++) {
            acc[i][0] = ffma2(ad[i], b0, acc[i][0]);
            acc[i][1] = ffma2(ad[i], b1, acc[i][1]);
            acc[i][2] = ffma2(ad[i], b2, acc[i][2]);
        }
    }

    #pragma unroll
    for (int i = 0; i < 4; i++) {
        int l = mb + m0 + i;
        __nv_bfloat16* o = Pout + ((size_t)(c * LL + l)) * KE;
        #pragma unroll
        for (int nl = 0; nl < 6; nl++) {
            int n = n0 + nl;
            if (n < P2) {
                float2 u = unpack2(acc[i][nl >> 1]);
                float s = (nl & 1) ? u.y : u.x;
                s = (s > 0.f) ? s : 0.2f * s;
                __nv_bfloat16 hb = __float2bfloat16(s);
                __nv_bfloat16 lb = __float2bfloat16(s - __bfloat162float(hb));
                o[n] = hb;
                if (z == 0) {               // A variant: hi, lo, hi
                    o[n + P2]     = lb;
                    o[n + 2 * P2] = hb;
                } else {                    // B variant: hi, hi, lo
                    o[n + P2]     = hb;
                    o[n + 2 * P2] = lb;
                }
            }
        }
    }

    // explicitly zero the K pad columns 243..255 for the 64 rows this block owns
    for (int idx = tid; idx < RT_BM * (KE - 3 * P2); idx += 256) {
        int r = idx / (KE - 3 * P2), cc = idx % (KE - 3 * P2);
        Pout[((size_t)(c * LL + mb + r)) * KE + 3 * P2 + cc] = __float2bfloat16(0.f);
    }
}

// ---------------- Kernel 3: att GEMM via mma.sync bf16 ---------------------
// CTA tile 128x128, K=256 resident. smem rows padded to 264 halves (528 B)
// -> conflict-free ldmatrix (4-bank rotation per row) and 16B-aligned rows.
#define ASTR 264
#define AT_SMEM (2 * 128 * ASTR * 2)      // 135168 B

__global__ __launch_bounds__(256, 1)
void att_mma(const __nv_bfloat16* __restrict__ pA,
             const __nv_bfloat16* __restrict__ pB,
             float* __restrict__ att) {
    extern __shared__ __nv_bfloat16 smb[];
    __nv_bfloat16* sA = smb;              // [128][264]
    __nv_bfloat16* sB = smb + 128 * ASTR; // [128][264]

    int tid  = threadIdx.x;
    int wid  = tid >> 5;
    int lane = tid & 31;
    int wm   = wid & 1;        // 0..1 (64-row slabs)
    int wn   = wid >> 1;       // 0..3 (32-col slabs)

    int c  = blockIdx.z;
    int mb = blockIdx.y * 128;
    int nb = blockIdx.x * 128;
    const char* Ab = (const char*)(pA + ((size_t)(c * LL + mb)) * KE);
    const char* Bb = (const char*)(pB + ((size_t)(c * LL + nb)) * KE);
    uint32_t sAu = smem_u32(sA);
    uint32_t sBu = smem_u32(sB);

    // ---- load both tiles (128 rows x 512 B each) via cp.async ----
    #pragma unroll
    for (int it = 0; it < 16; it++) {
        int idx  = it * 256 + tid;        // 0..4095
        int row  = idx >> 5;              // 0..127
        int ch   = idx & 31;              // 16B chunk 0..31
        cpa16(sAu + row * 528 + ch * 16, Ab + row * 512 + ch * 16);
        cpa16(sBu + row * 528 + ch * 16, Bb + row * 512 + ch * 16);
    }
    asm volatile("cp.async.commit_group;" ::: "memory");
    asm volatile("cp.async.wait_group 0;" ::: "memory");
    __syncthreads();

    // ---- MMA mainloop ----
    float acc[4][4][4];                   // [m-tile][n-tile][frag]
    #pragma unroll
    for (int i = 0; i < 4; i++)
        #pragma unroll
        for (int j = 0; j < 4; j++)
            #pragma unroll
            for (int q = 0; q < 4; q++) acc[i][j][q] = 0.f;

    int tr = lane & 15;                   // row within 16
    int tc = lane >> 4;                   // k-half selector
    uint32_t aBase = sAu + (wm * 64 + tr) * 528 + tc * 16;
    uint32_t bBase = sBu + (wn * 32 + tr) * 528 + tc * 16;

    #pragma unroll 4
    for (int kk = 0; kk < 16; kk++) {
        uint32_t koff = kk * 32;          // 16 halves = 32 B
        uint32_t afr[4][4];
        #pragma unroll
        for (int i = 0; i < 4; i++)
            ldmx4(afr[i][0], afr[i][1], afr[i][2], afr[i][3],
                  aBase + i * 16 * 528 + koff);
        uint32_t b0[4], b1[4];
        #pragma unroll
        for (int j = 0; j < 2; j++) {
            uint32_t r0, r1, r2, r3;
            ldmx4(r0, r1, r2, r3, bBase + j * 16 * 528 + koff);
            b0[j*2]   = r0; b1[j*2]   = r2;   // n-tile j*2   (rows +0..7)
            b0[j*2+1] = r1; b1[j*2+1] = r3;   // n-tile j*2+1 (rows +8..15)
        }
        #pragma unroll
        for (int i = 0; i < 4; i++)
            #pragma unroll
            for (int j = 0; j < 4; j++)
                mma16816(acc[i][j], afr[i], b0[j], b1[j]);
    }

    // ---- epilogue ----
    const float scale = 1.0f / 81.0f;
    int r0 = lane >> 2;                   // 0..7
    int c0 = (lane & 3) * 2;
    #pragma unroll
    for (int i = 0; i < 4; i++) {
        #pragma unroll
        for (int j = 0; j < 4; j++) {
            size_t row = (size_t)(mb + wm * 64 + i * 16 + r0);
            float* o = att + (size_t)c * LL * LL + row * LL
                     + nb + wn * 32 + j * 8 + c0;
            *(float2*)o            = make_float2(acc[i][j][0] * scale,
                                                 acc[i][j][1] * scale);
            *(float2*)(o + 8 * LL) = make_float2(acc[i][j][2] * scale,
                                                 acc[i][j][3] * scale);
        }
    }
}

// ---------------- launch ----------------
extern "C" void kernel_launch(void* const* d_in, const int* in_sizes, int n_in,
                              void* d_out, int out_size) {
    const float* x     = (const float*)d_in[0];
    const float* y     = (const float*)d_in[1];
    const float* W_img = (const float*)d_in[2];
    const float* b_img = (const float*)d_in[3];
    const float* W_fea = (const float*)d_in[4];
    const float* b_fea = (const float*)d_in[5];
    const float* W1    = (const float*)d_in[6];
    const float* W2    = (const float*)d_in[7];
    float* out = (float*)d_out;

    float *weT, *ux, *uy;
    __nv_bfloat16 *pA, *pB;
    cudaGetSymbolAddress((void**)&weT, g_wefft);
    cudaGetSymbolAddress((void**)&ux,  g_ux);
    cudaGetSymbolAddress((void**)&uy,  g_uy);
    cudaGetSymbolAddress((void**)&pA,  g_pA);
    cudaGetSymbolAddress((void**)&pB,  g_pB);

    static bool attr_set = false;
    if (!attr_set) {
        cudaFuncSetAttribute(att_mma, cudaFuncAttributeMaxDynamicSharedMemorySize,
                             AT_SMEM);
        cudaFuncSetAttribute(res_trans_kernel,
                             cudaFuncAttributeMaxDynamicSharedMemorySize, RT_SMEM);
        attr_set = true;
    }

    weff_kernel<<<P2, P2>>>(W1, W2, weT);
    {
        dim3 g(P2, LL / 256, 2);
        conv_unfold<<<g, 256>>>(x, y, W_img, b_img, W_fea, b_fea, ux, uy);
    }
    {
        dim3 g(LL / RT_BM, CH, 2);
        res_trans_kernel<<<g, 256, RT_SMEM>>>(ux, uy, pA, pB);
    }
    {
        dim3 g(LL / 128, LL / 128, CH);   // (8, 8, 32)
        att_mma<<<g, 256, AT_SMEM>>>(pA, pB, out);
    }
}

// round 7
// speedup vs baseline: 2.0880x; 1.2822x over previous
#include <cuda_runtime.h>
#include <cuda_bf16.h>
#include <cstdint>

// Shapes (fixed by the problem)
#define CH    32
#define DD    36
#define HH    48
#define WW    48
#define HW    (HH*WW)          // 2304
#define DHW   (DD*HW)          // 82944
#define PP    9
#define P2    81
#define ND    (DD/PP)          // 4
#define NW    (HW/PP)          // 256
#define LL    (ND*NW)          // 1024
#define M2    162              // 2*P2
#define KE    256              // extended K: [hi(81) | s1(81) | s2(81) | 13 zero pad]

// ---------------- device scratch (no allocs allowed) ----------------
__device__ float g_wefft[P2 * P2];                  // Wefft[j][k] = (W2@W1)[k][j]
__device__ float g_ux[CH * P2 * LL];                // Ut[c][j][l] (K-major, fp32)
__device__ float g_uy[CH * P2 * LL];
__device__ __nv_bfloat16 g_pA[CH * LL * KE];        // A rows: [hi, lo, hi, 0]
__device__ __nv_bfloat16 g_pB[CH * LL * KE];        // B rows: [hi, hi, lo, 0]

// ---------------- f32x2 packed math helpers ----------------
__device__ __forceinline__ unsigned long long ffma2(unsigned long long a,
                                                    unsigned long long b,
                                                    unsigned long long c) {
    unsigned long long d;
    asm("fma.rn.f32x2 %0, %1, %2, %3;" : "=l"(d) : "l"(a), "l"(b), "l"(c));
    return d;
}
__device__ __forceinline__ unsigned long long dup2(float a) {
    unsigned long long d;
    asm("mov.b64 %0, {%1, %1};" : "=l"(d) : "f"(a));
    return d;
}
__device__ __forceinline__ float2 unpack2(unsigned long long v) {
    float2 r;
    asm("mov.b64 {%0, %1}, %2;" : "=f"(r.x), "=f"(r.y) : "l"(v));
    return r;
}

// ---------------- async / mma helpers (plain-target safe) ----------------
__device__ __forceinline__ uint32_t smem_u32(const void* p) {
    uint32_t a;
    asm("{ .reg .u64 t; cvta.to.shared.u64 t, %1; cvt.u32.u64 %0, t; }"
        : "=r"(a) : "l"(p));
    return a;
}
__device__ __forceinline__ void cpa16(uint32_t s, const void* g) {
    asm volatile("cp.async.cg.shared.global [%0], [%1], 16;" :: "r"(s), "l"(g));
}
__device__ __forceinline__ void ldmx4(uint32_t& r0, uint32_t& r1,
                                      uint32_t& r2, uint32_t& r3, uint32_t a) {
    asm volatile("ldmatrix.sync.aligned.m8n8.x4.shared.b16 {%0,%1,%2,%3}, [%4];"
                 : "=r"(r0), "=r"(r1), "=r"(r2), "=r"(r3) : "r"(a));
}
__device__ __forceinline__ void mma16816(float* d, const uint32_t* a,
                                         uint32_t b0, uint32_t b1) {
    asm volatile(
        "mma.sync.aligned.m16n8k16.row.col.f32.bf16.bf16.f32 "
        "{%0,%1,%2,%3}, {%4,%5,%6,%7}, {%8,%9}, {%0,%1,%2,%3};"
        : "+f"(d[0]), "+f"(d[1]), "+f"(d[2]), "+f"(d[3])
        : "r"(a[0]), "r"(a[1]), "r"(a[2]), "r"(a[3]), "r"(b0), "r"(b1));
}

// ---------------- Kernel 0: Wefft[j][k] = (W2 @ W1)[k][j] ----------------
__global__ void weff_kernel(const float* __restrict__ W1,
                            const float* __restrict__ W2,
                            float* __restrict__ WeT) {
    __shared__ float w2row[M2];
    int k = blockIdx.x;
    int j = threadIdx.x;
    for (int m = j; m < M2; m += P2) w2row[m] = W2[k * M2 + m];
    __syncthreads();
    float s = 0.f;
    #pragma unroll 6
    for (int m = 0; m < M2; m++) s += w2row[m] * W1[m * P2 + j];
    WeT[j * P2 + k] = s;
}

// ---------------- Kernel 1: 1x1x1 conv + unfold, K-major, x/y merged ------
__global__ __launch_bounds__(256)
void conv_unfold(const float* __restrict__ x, const float* __restrict__ y,
                 const float* __restrict__ Wi, const float* __restrict__ bi,
                 const float* __restrict__ Wf, const float* __restrict__ bf_,
                 float* __restrict__ ux, float* __restrict__ uy) {
    int z = blockIdx.z;
    const float* src = z ? y : x;
    const float* Wc  = z ? Wf : Wi;
    const float* bc  = z ? bf_ : bi;
    float* U         = z ? uy : ux;

    __shared__ float Ws[CH * CH];
    __shared__ float bs[CH];
    int tid = threadIdx.x;
    for (int i = tid; i < CH * CH; i += 256) Ws[i] = Wc[i];
    if (tid < CH) bs[tid] = bc[tid];
    __syncthreads();

    int j  = blockIdx.x;                // 0..80
    int l  = blockIdx.y * 256 + tid;    // 0..1023
    int kd = j / PP, kw = j - kd * PP;
    int pd = l >> 8, pw = l & 255;
    int p  = (pd * PP + kd) * HW + pw * PP + kw;

    float xv[CH];
    #pragma unroll
    for (int i = 0; i < CH; i++) xv[i] = src[i * DHW + p];

    #pragma unroll 4
    for (int c = 0; c < CH; c++) {
        const float4* wr = (const float4*)&Ws[c * CH];
        float s = bs[c];
        #pragma unroll
        for (int q = 0; q < CH / 4; q++) {
            float4 w = wr[q];
            s += w.x * xv[4*q] + w.y * xv[4*q+1] + w.z * xv[4*q+2] + w.w * xv[4*q+3];
        }
        U[(c * P2 + j) * LL + l] = s;
    }
}

// ---------------- Kernel 2: folded res_trans + LeakyReLU + bf16 split -----
// out row (c,l): bf16[256]  A-variant: [hi|lo|hi|0]  B-variant: [hi|hi|lo|0]
// Results staged in smem (reusing the As region) then copied out with 16B stores.
#define RT_BM 64
#define RT_SMEM ((P2 * RT_BM + P2 * 96) * 4)     // 51840 B
__global__ __launch_bounds__(256)
void res_trans_kernel(const float* __restrict__ U0, const float* __restrict__ U1,
                      __nv_bfloat16* __restrict__ P0, __nv_bfloat16* __restrict__ P1) {
    extern __shared__ float sm[];
    float* As = sm;                   // [81][64]
    float* Bs = sm + P2 * RT_BM;      // [81][96] (cols >= 81 zero)

    int z  = blockIdx.z;
    const float* U = z ? U1 : U0;
    __nv_bfloat16* Pout = z ? P1 : P0;

    int c  = blockIdx.y;
    int mb = blockIdx.x * RT_BM;
    int tid = threadIdx.x;
    const float* A = U + c * (P2 * LL);

    for (int idx = tid; idx < P2 * RT_BM; idx += 256) {
        int jj = idx >> 6, m = idx & 63;
        As[idx] = A[jj * LL + mb + m];
    }
    for (int idx = tid; idx < P2 * 96; idx += 256) {
        int jj = idx / 96, n = idx - jj * 96;
        Bs[idx] = (n < P2) ? g_wefft[jj * P2 + n] : 0.f;
    }
    __syncthreads();

    int tx = tid & 15, ty = tid >> 4;
    int m0 = ty * 4, n0 = tx * 6;

    unsigned long long acc[4][3];
    #pragma unroll
    for (int i = 0; i < 4; i++)
        #pragma unroll
        for (int jj = 0; jj < 3; jj++) acc[i][jj] = 0ull;

    #pragma unroll 3
    for (int j = 0; j < P2; j++) {
        float4 a0 = *(const float4*)(As + j * RT_BM + m0);
        const unsigned long long* bp =
            (const unsigned long long*)(Bs + j * 96 + n0);
        unsigned long long b0 = bp[0], b1 = bp[1], b2 = bp[2];
        unsigned long long ad[4];
        ad[0] = dup2(a0.x); ad[1] = dup2(a0.y); ad[2] = dup2(a0.z); ad[3] = dup2(a0.w);
        #pragma unroll
        for (int i = 0; i < 4; i++) {
            acc[i][0] = ffma2(ad[i], b0, acc[i][0]);
            acc[i][1] = ffma2(ad[i], b1, acc[i][1]);
            acc[i][2] = ffma2(ad[i], b2, acc[i][2]);
        }
    }

    __syncthreads();                          // done reading As/Bs
    __nv_bfloat16* st = (__nv_bfloat16*)sm;   // staging [64][256] bf16 = 32 KB

    // zero the K pad columns 243..255
    for (int idx = tid; idx < RT_BM * (KE - 3 * P2); idx += 256) {
        int r = idx / (KE - 3 * P2), cc = idx - r * (KE - 3 * P2);
        st[r * KE + 3 * P2 + cc] = __float2bfloat16(0.f);
    }

    #pragma unroll
    for (int i = 0; i < 4; i++) {
        __nv_bfloat16* o = st + (m0 + i) * KE;
        #pragma unroll
        for (int nl = 0; nl < 6; nl++) {
            int n = n0 + nl;
            if (n < P2) {
                float2 u = unpack2(acc[i][nl >> 1]);
                float s = (nl & 1) ? u.y : u.x;
                s = (s > 0.f) ? s : 0.2f * s;
                __nv_bfloat16 hb = __float2bfloat16(s);
                __nv_bfloat16 lb = __float2bfloat16(s - __bfloat162float(hb));
                o[n] = hb;
                if (z == 0) {               // A variant: hi, lo, hi
                    o[n + P2]     = lb;
                    o[n + 2 * P2] = hb;
                } else {                    // B variant: hi, hi, lo
                    o[n + P2]     = hb;
                    o[n + 2 * P2] = lb;
                }
            }
        }
    }
    __syncthreads();

    // coalesced copy-out: 64 rows x 512 B
    const uint4* s4 = (const uint4*)st;
    uint4* g4 = (uint4*)(Pout + ((size_t)(c * LL + mb)) * KE);
    #pragma unroll
    for (int i = 0; i < 8; i++) g4[i * 256 + tid] = s4[i * 256 + tid];
}

// ---------------- Kernel 3: att GEMM via mma.sync bf16, pipelined ----------
// CTA tile 128x128; K=256 in 4 chunks of 64; 3-stage cp.async pipeline.
// Stage: A 128x128B + B 128x128B = 32 KB, XOR-swizzled (chunk ^= row&7).
#define AT_STAGE 32768
#define AT_SMEM  (3 * AT_STAGE)      // 98304 B

__device__ __forceinline__ void att_load_chunk(uint32_t sAb, uint32_t sBb,
                                               const char* Ab, const char* Bb,
                                               int ck, int tid) {
    #pragma unroll
    for (int it = 0; it < 4; it++) {
        int idx = it * 256 + tid;          // 0..1023
        int row = idx >> 3, ch = idx & 7;
        int chs = ch ^ (row & 7);
        cpa16(sAb + row * 128 + chs * 16, Ab + row * 512 + ck * 128 + ch * 16);
        cpa16(sBb + row * 128 + chs * 16, Bb + row * 512 + ck * 128 + ch * 16);
    }
    asm volatile("cp.async.commit_group;" ::: "memory");
}

__global__ __launch_bounds__(256, 2)
void att_mma(const __nv_bfloat16* __restrict__ pA,
             const __nv_bfloat16* __restrict__ pB,
             float* __restrict__ att) {
    extern __shared__ char smb[];
    uint32_t sbase = smem_u32(smb);

    int tid  = threadIdx.x;
    int wid  = tid >> 5;
    int lane = tid & 31;
    int wm   = wid & 1;        // 0..1 (64-row slabs)
    int wn   = wid >> 1;       // 0..3 (32-col slabs)

    int c  = blockIdx.z;
    int mb = blockIdx.y * 128;
    int nb = blockIdx.x * 128;
    const char* Ab = (const char*)(pA + ((size_t)(c * LL + mb)) * KE);
    const char* Bb = (const char*)(pB + ((size_t)(c * LL + nb)) * KE);

    // prefetch chunks 0,1,2 into stages 0,1,2
    att_load_chunk(sbase,                sbase + 16384,                Ab, Bb, 0, tid);
    att_load_chunk(sbase + AT_STAGE,     sbase + AT_STAGE + 16384,     Ab, Bb, 1, tid);
    att_load_chunk(sbase + 2*AT_STAGE,   sbase + 2*AT_STAGE + 16384,   Ab, Bb, 2, tid);

    float acc[4][4][4];
    #pragma unroll
    for (int i = 0; i < 4; i++)
        #pragma unroll
        for (int j = 0; j < 4; j++)
            #pragma unroll
            for (int q = 0; q < 4; q++) acc[i][j][q] = 0.f;

    int tr  = lane & 15;                  // row within 16
    int tc  = lane >> 4;                  // k-half selector (16B chunk parity)
    int xorv = tr & 7;

    #pragma unroll
    for (int ck = 0; ck < 4; ck++) {
        if (ck == 0)      asm volatile("cp.async.wait_group 2;" ::: "memory");
        else if (ck == 1) asm volatile("cp.async.wait_group 2;" ::: "memory");
        else if (ck == 2) asm volatile("cp.async.wait_group 1;" ::: "memory");
        else              asm volatile("cp.async.wait_group 0;" ::: "memory");
        __syncthreads();

        uint32_t sAb = sbase + (ck % 3) * AT_STAGE;
        uint32_t sBb = sAb + 16384;
        uint32_t aRow = sAb + (wm * 64 + tr) * 128;
        uint32_t bRow = sBb + (wn * 32 + tr) * 128;

        #pragma unroll
        for (int kk2 = 0; kk2 < 4; kk2++) {
            uint32_t chs = (uint32_t)(((kk2 * 2 + tc) ^ xorv) << 4);
            uint32_t afr[4][4];
            #pragma unroll
            for (int i = 0; i < 4; i++)
                ldmx4(afr[i][0], afr[i][1], afr[i][2], afr[i][3],
                      aRow + i * 2048 + chs);
            uint32_t b0[4], b1[4];
            #pragma unroll
            for (int j = 0; j < 2; j++) {
                uint32_t r0, r1, r2, r3;
                ldmx4(r0, r1, r2, r3, bRow + j * 2048 + chs);
                b0[j*2]   = r0; b1[j*2]   = r2;
                b0[j*2+1] = r1; b1[j*2+1] = r3;
            }
            #pragma unroll
            for (int i = 0; i < 4; i++)
                #pragma unroll
                for (int j = 0; j < 4; j++)
                    mma16816(acc[i][j], afr[i], b0[j], b1[j]);
        }

        if (ck == 0) {
            __syncthreads();   // stage 0 fully consumed by all warps
            att_load_chunk(sbase, sbase + 16384, Ab, Bb, 3, tid);
        }
    }

    // ---- epilogue ----
    const float scale = 1.0f / 81.0f;
    int r0 = lane >> 2;
    int c0 = (lane & 3) * 2;
    #pragma unroll
    for (int i = 0; i < 4; i++) {
        #pragma unroll
        for (int j = 0; j < 4; j++) {
            size_t row = (size_t)(mb + wm * 64 + i * 16 + r0);
            float* o = att + (size_t)c * LL * LL + row * LL
                     + nb + wn * 32 + j * 8 + c0;
            *(float2*)o            = make_float2(acc[i][j][0] * scale,
                                                 acc[i][j][1] * scale);
            *(float2*)(o + 8 * LL) = make_float2(acc[i][j][2] * scale,
                                                 acc[i][j][3] * scale);
        }
    }
}

// ---------------- launch ----------------
extern "C" void kernel_launch(void* const* d_in, const int* in_sizes, int n_in,
                              void* d_out, int out_size) {
    const float* x     = (const float*)d_in[0];
    const float* y     = (const float*)d_in[1];
    const float* W_img = (const float*)d_in[2];
    const float* b_img = (const float*)d_in[3];
    const float* W_fea = (const float*)d_in[4];
    const float* b_fea = (const float*)d_in[5];
    const float* W1    = (const float*)d_in[6];
    const float* W2    = (const float*)d_in[7];
    float* out = (float*)d_out;

    float *weT, *ux, *uy;
    __nv_bfloat16 *pA, *pB;
    cudaGetSymbolAddress((void**)&weT, g_wefft);
    cudaGetSymbolAddress((void**)&ux,  g_ux);
    cudaGetSymbolAddress((void**)&uy,  g_uy);
    cudaGetSymbolAddress((void**)&pA,  g_pA);
    cudaGetSymbolAddress((void**)&pB,  g_pB);

    static bool attr_set = false;
    if (!attr_set) {
        cudaFuncSetAttribute(att_mma, cudaFuncAttributeMaxDynamicSharedMemorySize,
                             AT_SMEM);
        cudaFuncSetAttribute(res_trans_kernel,
                             cudaFuncAttributeMaxDynamicSharedMemorySize, RT_SMEM);
        attr_set = true;
    }

    weff_kernel<<<P2, P2>>>(W1, W2, weT);
    {
        dim3 g(P2, LL / 256, 2);
        conv_unfold<<<g, 256>>>(x, y, W_img, b_img, W_fea, b_fea, ux, uy);
    }
    {
        dim3 g(LL / RT_BM, CH, 2);
        res_trans_kernel<<<g, 256, RT_SMEM>>>(ux, uy, pA, pB);
    }
    {
        dim3 g(LL / 128, LL / 128, CH);   // (8, 8, 32)
        att_mma<<<g, 256, AT_SMEM>>>(pA, pB, out);
    }
}

// round 8
// speedup vs baseline: 2.4972x; 1.1960x over previous
#include <cuda_runtime.h>
#include <cuda_fp16.h>
#include <cstdint>

// Shapes (fixed by the problem)
#define CH    32
#define DD    36
#define HH    48
#define WW    48
#define HW    (HH*WW)          // 2304
#define DHW   (DD*HW)          // 82944
#define PP    9
#define P2    81
#define ND    (DD/PP)          // 4
#define NW    (HW/PP)          // 256
#define LL    (ND*NW)          // 1024
#define M2    162              // 2*P2
#define KE    192              // extended K: [hi(81) | lo(81) | 30 zero pad]
#define VSCALE 1024.0f         // pre-scale so lo stays in fp16 normal range

// ---------------- device scratch (no allocs allowed) ----------------
__device__ float g_wefft[P2 * P2];            // Wefft[j][k] = (W2@W1)[k][j]
__device__ float g_ux[CH * P2 * LL];          // Ut[c][j][l] (K-major, fp32)
__device__ float g_uy[CH * P2 * LL];
__device__ __half g_pA[CH * LL * KE];         // rows: [hi(81) | lo(81) | 0]
__device__ __half g_pB[CH * LL * KE];

// ---------------- f32x2 packed math helpers ----------------
__device__ __forceinline__ unsigned long long ffma2(unsigned long long a,
                                                    unsigned long long b,
                                                    unsigned long long c) {
    unsigned long long d;
    asm("fma.rn.f32x2 %0, %1, %2, %3;" : "=l"(d) : "l"(a), "l"(b), "l"(c));
    return d;
}
__device__ __forceinline__ unsigned long long dup2(float a) {
    unsigned long long d;
    asm("mov.b64 %0, {%1, %1};" : "=l"(d) : "f"(a));
    return d;
}
__device__ __forceinline__ float2 unpack2(unsigned long long v) {
    float2 r;
    asm("mov.b64 {%0, %1}, %2;" : "=f"(r.x), "=f"(r.y) : "l"(v));
    return r;
}

// ---------------- async / mma helpers (plain-target safe) ----------------
__device__ __forceinline__ uint32_t smem_u32(const void* p) {
    uint32_t a;
    asm("{ .reg .u64 t; cvta.to.shared.u64 t, %1; cvt.u32.u64 %0, t; }"
        : "=r"(a) : "l"(p));
    return a;
}
__device__ __forceinline__ void cpa16(uint32_t s, const void* g) {
    asm volatile("cp.async.cg.shared.global [%0], [%1], 16;" :: "r"(s), "l"(g));
}
__device__ __forceinline__ void ldmx4(uint32_t& r0, uint32_t& r1,
                                      uint32_t& r2, uint32_t& r3, uint32_t a) {
    asm volatile("ldmatrix.sync.aligned.m8n8.x4.shared.b16 {%0,%1,%2,%3}, [%4];"
                 : "=r"(r0), "=r"(r1), "=r"(r2), "=r"(r3) : "r"(a));
}
__device__ __forceinline__ void mma16816(float* d, const uint32_t* a,
                                         uint32_t b0, uint32_t b1) {
    asm volatile(
        "mma.sync.aligned.m16n8k16.row.col.f32.f16.f16.f32 "
        "{%0,%1,%2,%3}, {%4,%5,%6,%7}, {%8,%9}, {%0,%1,%2,%3};"
        : "+f"(d[0]), "+f"(d[1]), "+f"(d[2]), "+f"(d[3])
        : "r"(a[0]), "r"(a[1]), "r"(a[2]), "r"(a[3]), "r"(b0), "r"(b1));
}

// ---------------- Kernel 0: Wefft[j][k] = (W2 @ W1)[k][j] ----------------
__global__ void weff_kernel(const float* __restrict__ W1,
                            const float* __restrict__ W2,
                            float* __restrict__ WeT) {
    __shared__ float w2row[M2];
    int k = blockIdx.x;
    int j = threadIdx.x;
    for (int m = j; m < M2; m += P2) w2row[m] = W2[k * M2 + m];
    __syncthreads();
    float s = 0.f;
    #pragma unroll 6
    for (int m = 0; m < M2; m++) s += w2row[m] * W1[m * P2 + j];
    WeT[j * P2 + k] = s;
}

// ---------------- Kernel 1: conv + unfold via smem transpose --------------
// Block: one d-slice (fixed pd,kd), 32 pw values -> 288 voxels, all 32 out ch.
// Coalesced float4 reads of x, conv from smem, staged, coalesced float4 writes.
#define CV_THREADS 288
#define CV_SMEM ((9216 + 9216 + 1024 + 32) * 4)    // xs + us + ws + bs = 73984 B
__global__ __launch_bounds__(CV_THREADS)
void conv_unfold(const float* __restrict__ x, const float* __restrict__ y,
                 const float* __restrict__ Wi, const float* __restrict__ bi,
                 const float* __restrict__ Wf, const float* __restrict__ bf_,
                 float* __restrict__ ux, float* __restrict__ uy) {
    extern __shared__ float cs[];
    float* xs = cs;            // [32][288]
    float* us = cs + 9216;     // [32][288]
    float* ws = cs + 18432;    // [32][32]
    float* bs = cs + 19456;    // [32]

    int z = blockIdx.z;
    const float* src = z ? y : x;
    const float* Wc  = z ? Wf : Wi;
    const float* bc  = z ? bf_ : bi;
    float* U         = z ? uy : ux;

    int tid = threadIdx.x;
    int d   = blockIdx.x;              // 0..35
    int pwb = blockIdx.y;              // 0..7
    int pd = d / PP, kd = d - pd * PP;

    for (int i = tid; i < CH * CH; i += CV_THREADS) ws[i] = Wc[i];
    if (tid < CH) bs[tid] = bc[tid];

    // coalesced load: 32 ch x 288 floats (72 float4 per ch)
    {
        const float4* x4 = (const float4*)src;
        float4* xs4 = (float4*)xs;
        int base = d * (HW / 4) + pwb * 72;
        #pragma unroll
        for (int it = 0; it < 8; it++) {
            int idx = it * CV_THREADS + tid;       // 0..2303
            int i = idx / 72, q = idx - i * 72;
            xs4[idx] = x4[i * (DHW / 4) + base + q];
        }
    }
    __syncthreads();

    // conv: each thread owns one voxel
    {
        int v = tid;                   // 0..287
        float xv[CH];
        #pragma unroll
        for (int i = 0; i < CH; i++) xv[i] = xs[i * 288 + v];
        #pragma unroll 4
        for (int c = 0; c < CH; c++) {
            float s = bs[c];
            #pragma unroll
            for (int i = 0; i < CH; i++) s += ws[c * CH + i] * xv[i];
            us[c * 288 + v] = s;
        }
    }
    __syncthreads();

    // coalesced write-out: rows (c,kw) of 32 l-values (8 float4)
    {
        int l0 = pd * NW + pwb * 32;
        #pragma unroll
        for (int it = 0; it < 8; it++) {
            int idx = it * CV_THREADS + tid;       // 0..2303
            int row = idx >> 3, q = idx & 7;       // row: c*9+kw
            int c = row / PP, kw = row - c * PP;
            int vb = q * 4 * PP + kw;
            float4 f = make_float4(us[c * 288 + vb],
                                   us[c * 288 + vb + 9],
                                   us[c * 288 + vb + 18],
                                   us[c * 288 + vb + 27]);
            float4* g4 = (float4*)(U + ((size_t)(c * P2 + kd * PP + kw)) * LL + l0);
            g4[q] = f;
        }
    }
}

// ---------------- Kernel 2: folded res_trans + LeakyReLU + fp16 split -----
// out row (c,l): fp16[192] = [hi(81) | lo(81) | 0], values pre-scaled by 1024.
#define RT_BM 64
#define RT_SMEM ((P2 * RT_BM + P2 * 96) * 4)     // 51840 B
__global__ __launch_bounds__(256)
void res_trans_kernel(const float* __restrict__ U0, const float* __restrict__ U1,
                      __half* __restrict__ P0, __half* __restrict__ P1) {
    extern __shared__ float sm[];
    float* As = sm;                   // [81][64]
    float* Bs = sm + P2 * RT_BM;      // [81][96] (cols >= 81 zero)

    int z  = blockIdx.z;
    const float* U = z ? U1 : U0;
    __half* Pout = z ? P1 : P0;

    int c  = blockIdx.y;
    int mb = blockIdx.x * RT_BM;
    int tid = threadIdx.x;
    const float* A = U + c * (P2 * LL);

    for (int idx = tid; idx < P2 * RT_BM; idx += 256) {
        int jj = idx >> 6, m = idx & 63;
        As[idx] = A[jj * LL + mb + m];
    }
    for (int idx = tid; idx < P2 * 96; idx += 256) {
        int jj = idx / 96, n = idx - jj * 96;
        Bs[idx] = (n < P2) ? g_wefft[jj * P2 + n] : 0.f;
    }
    __syncthreads();

    int tx = tid & 15, ty = tid >> 4;
    int m0 = ty * 4, n0 = tx * 6;

    unsigned long long acc[4][3];
    #pragma unroll
    for (int i = 0; i < 4; i++)
        #pragma unroll
        for (int jj = 0; jj < 3; jj++) acc[i][jj] = 0ull;

    #pragma unroll 3
    for (int j = 0; j < P2; j++) {
        float4 a0 = *(const float4*)(As + j * RT_BM + m0);
        const unsigned long long* bp =
            (const unsigned long long*)(Bs + j * 96 + n0);
        unsigned long long b0 = bp[0], b1 = bp[1], b2 = bp[2];
        unsigned long long ad[4];
        ad[0] = dup2(a0.x); ad[1] = dup2(a0.y); ad[2] = dup2(a0.z); ad[3] = dup2(a0.w);
        #pragma unroll
        for (int i = 0; i < 4; i++) {
            acc[i][0] = ffma2(ad[i], b0, acc[i][0]);
            acc[i][1] = ffma2(ad[i], b1, acc[i][1]);
            acc[i][2] = ffma2(ad[i], b2, acc[i][2]);
        }
    }

    __syncthreads();                  // done reading As/Bs
    __half* st = (__half*)sm;         // staging [64][192] fp16 = 24576 B

    // zero pad cols 162..191
    for (int idx = tid; idx < RT_BM * (KE - 2 * P2); idx += 256) {
        int r = idx / (KE - 2 * P2), cc = idx - r * (KE - 2 * P2);
        st[r * KE + 2 * P2 + cc] = __float2half(0.f);
    }

    #pragma unroll
    for (int i = 0; i < 4; i++) {
        __half* o = st + (m0 + i) * KE;
        #pragma unroll
        for (int nl = 0; nl < 6; nl++) {
            int n = n0 + nl;
            if (n < P2) {
                float2 u = unpack2(acc[i][nl >> 1]);
                float s = (nl & 1) ? u.y : u.x;
                s = (s > 0.f) ? s : 0.2f * s;
                s *= VSCALE;
                __half hb = __float2half_rn(s);
                __half lb = __float2half_rn(s - __half2float(hb));
                o[n]      = hb;
                o[n + P2] = lb;
            }
        }
    }
    __syncthreads();

    // coalesced copy-out: 64 rows x 384 B = 1536 uint4
    const uint4* s4 = (const uint4*)st;
    uint4* g4 = (uint4*)(Pout + ((size_t)(c * LL + mb)) * KE);
    #pragma unroll
    for (int i = 0; i < 6; i++) g4[i * 256 + tid] = s4[i * 256 + tid];
}

// ---------------- Kernel 3: att GEMM via mma.sync fp16, pipelined ----------
// CTA tile 128x128; K=192 in exactly 3 chunks of 64 = 3 stages (no reuse).
// Stage: A 128x128B + B 128x128B = 32 KB, XOR-swizzled (chunk ^= row&7).
#define AT_STAGE 32768
#define AT_SMEM  (3 * AT_STAGE)      // 98304 B

__device__ __forceinline__ void att_load_chunk(uint32_t sAb, uint32_t sBb,
                                               const char* Ab, const char* Bb,
                                               int ck, int tid) {
    #pragma unroll
    for (int it = 0; it < 4; it++) {
        int idx = it * 256 + tid;          // 0..1023
        int row = idx >> 3, ch = idx & 7;
        int chs = ch ^ (row & 7);
        cpa16(sAb + row * 128 + chs * 16, Ab + row * 384 + ck * 128 + ch * 16);
        cpa16(sBb + row * 128 + chs * 16, Bb + row * 384 + ck * 128 + ch * 16);
    }
    asm volatile("cp.async.commit_group;" ::: "memory");
}

__global__ __launch_bounds__(256, 2)
void att_mma(const __half* __restrict__ pA,
             const __half* __restrict__ pB,
             float* __restrict__ att) {
    extern __shared__ char smb[];
    uint32_t sbase = smem_u32(smb);

    int tid  = threadIdx.x;
    int wid  = tid >> 5;
    int lane = tid & 31;
    int wm   = wid & 1;        // 0..1 (64-row slabs)
    int wn   = wid >> 1;       // 0..3 (32-col slabs)

    int c  = blockIdx.z;
    int mb = blockIdx.y * 128;
    int nb = blockIdx.x * 128;
    const char* Ab = (const char*)(pA + ((size_t)(c * LL + mb)) * KE);
    const char* Bb = (const char*)(pB + ((size_t)(c * LL + nb)) * KE);

    att_load_chunk(sbase,              sbase + 16384,              Ab, Bb, 0, tid);
    att_load_chunk(sbase + AT_STAGE,   sbase + AT_STAGE + 16384,   Ab, Bb, 1, tid);
    att_load_chunk(sbase + 2*AT_STAGE, sbase + 2*AT_STAGE + 16384, Ab, Bb, 2, tid);

    float acc[4][4][4];
    #pragma unroll
    for (int i = 0; i < 4; i++)
        #pragma unroll
        for (int j = 0; j < 4; j++)
            #pragma unroll
            for (int q = 0; q < 4; q++) acc[i][j][q] = 0.f;

    int tr   = lane & 15;                 // row within 16
    int tc   = lane >> 4;                 // 16B-half selector
    int xorv = tr & 7;

    #pragma unroll
    for (int ck = 0; ck < 3; ck++) {
        if (ck == 0)      asm volatile("cp.async.wait_group 2;" ::: "memory");
        else if (ck == 1) asm volatile("cp.async.wait_group 1;" ::: "memory");
        else              asm volatile("cp.async.wait_group 0;" ::: "memory");
        __syncthreads();

        uint32_t sAb = sbase + ck * AT_STAGE;
        uint32_t sBb = sAb + 16384;
        uint32_t aRow = sAb + (wm * 64 + tr) * 128;
        uint32_t bRow = sBb + (wn * 32 + tr) * 128;

        #pragma unroll
        for (int kk2 = 0; kk2 < 4; kk2++) {
            uint32_t chs = (uint32_t)(((kk2 * 2 + tc) ^ xorv) << 4);
            uint32_t afr[4][4];
            #pragma unroll
            for (int i = 0; i < 4; i++)
                ldmx4(afr[i][0], afr[i][1], afr[i][2], afr[i][3],
                      aRow + i * 2048 + chs);
            uint32_t b0[4], b1[4];
            #pragma unroll
            for (int j = 0; j < 2; j++) {
                uint32_t r0, r1, r2, r3;
                ldmx4(r0, r1, r2, r3, bRow + j * 2048 + chs);
                b0[j*2]   = r0; b1[j*2]   = r2;
                b0[j*2+1] = r1; b1[j*2+1] = r3;
            }
            #pragma unroll
            for (int i = 0; i < 4; i++)
                #pragma unroll
                for (int j = 0; j < 4; j++)
                    mma16816(acc[i][j], afr[i], b0[j], b1[j]);
        }
    }

    // ---- epilogue ----  product carries VSCALE^2 = 2^20
    const float scale = 1.0f / (81.0f * 1048576.0f);
    int r0 = lane >> 2;
    int c0 = (lane & 3) * 2;
    #pragma unroll
    for (int i = 0; i < 4; i++) {
        #pragma unroll
        for (int j = 0; j < 4; j++) {
            size_t row = (size_t)(mb + wm * 64 + i * 16 + r0);
            float* o = att + (size_t)c * LL * LL + row * LL
                     + nb + wn * 32 + j * 8 + c0;
            *(float2*)o            = make_float2(acc[i][j][0] * scale,
                                                 acc[i][j][1] * scale);
            *(float2*)(o + 8 * LL) = make_float2(acc[i][j][2] * scale,
                                                 acc[i][j][3] * scale);
        }
    }
}

// ---------------- launch ----------------
extern "C" void kernel_launch(void* const* d_in, const int* in_sizes, int n_in,
                              void* d_out, int out_size) {
    const float* x     = (const float*)d_in[0];
    const float* y     = (const float*)d_in[1];
    const float* W_img = (const float*)d_in[2];
    const float* b_img = (const float*)d_in[3];
    const float* W_fea = (const float*)d_in[4];
    const float* b_fea = (const float*)d_in[5];
    const float* W1    = (const float*)d_in[6];
    const float* W2    = (const float*)d_in[7];
    float* out = (float*)d_out;

    float *weT, *ux, *uy;
    __half *pA, *pB;
    cudaGetSymbolAddress((void**)&weT, g_wefft);
    cudaGetSymbolAddress((void**)&ux,  g_ux);
    cudaGetSymbolAddress((void**)&uy,  g_uy);
    cudaGetSymbolAddress((void**)&pA,  g_pA);
    cudaGetSymbolAddress((void**)&pB,  g_pB);

    static bool attr_set = false;
    if (!attr_set) {
        cudaFuncSetAttribute(att_mma, cudaFuncAttributeMaxDynamicSharedMemorySize,
                             AT_SMEM);
        cudaFuncSetAttribute(res_trans_kernel,
                             cudaFuncAttributeMaxDynamicSharedMemorySize, RT_SMEM);
        cudaFuncSetAttribute(conv_unfold,
                             cudaFuncAttributeMaxDynamicSharedMemorySize, CV_SMEM);
        attr_set = true;
    }

    weff_kernel<<<P2, P2>>>(W1, W2, weT);
    {
        dim3 g(DD, 8, 2);                 // d-slice x pw-block x {x,y}
        conv_unfold<<<g, CV_THREADS, CV_SMEM>>>(x, y, W_img, b_img,
                                                W_fea, b_fea, ux, uy);
    }
    {
        dim3 g(LL / RT_BM, CH, 2);
        res_trans_kernel<<<g, 256, RT_SMEM>>>(ux, uy, pA, pB);
    }
    {
        dim3 g(LL / 128, LL / 128, CH);   // (8, 8, 32)
        att_mma<<<g, 256, AT_SMEM>>>(pA, pB, out);
    }
}